// round 15
// baseline (speedup 1.0000x reference)
#include <cuda_runtime.h>
#include <cuda_fp16.h>
#include <math.h>
#include <stdint.h>

#define BB 2048
#define HH 256
#define TT 256
#define LN_EPS 1e-5f
#define NJOBS 544
#define BUFB 25600

// ---------------- persistent device scratch (no allocations) ----------------
__device__ float g_C0[BB * HH], g_C1[BB * HH];
__device__ __align__(16) __half g_H0h[2][BB * HH], g_H0l[2][BB * HH];
__device__ __align__(16) __half g_H1h[2][BB * HH], g_H1l[2][BB * HH];
__device__ float g_XP0[BB * 4 * HH];
__device__ float g_E1[BB * 128], g_ENC[BB * HH];
// fp16 weight images: gate-interleaved row-major [tile][n][K], single plane
__device__ __align__(16) __half g_I0[8 * 128 * 256];   // Whh0
__device__ __align__(16) __half g_I1[8 * 128 * 512];   // [Wih1 | Whh1]
__device__ __align__(16) __half g_I3[128 * 256];       // W3
__device__ unsigned g_ticket[TT + 2];
__device__ unsigned g_barcnt;

__device__ __forceinline__ float geluf(float v) {
    return 0.5f * v * (1.0f + erff(v * 0.7071067811865476f));
}
__device__ __forceinline__ float sigf(float v) { return 1.0f / (1.0f + expf(-v)); }

__device__ __forceinline__ uint32_t smem_u32(const void* p) {
    uint32_t a;
    asm("{ .reg .u64 t; cvta.to.shared.u64 t, %1; cvt.u32.u64 %0, t; }" : "=r"(a) : "l"(p));
    return a;
}
__device__ __forceinline__ float ld32cg(const float* p) {
    float v; asm volatile("ld.global.cg.f32 %0, [%1];" : "=f"(v) : "l"(p)); return v;
}
__device__ __forceinline__ void st32cg(float* p, float v) {
    asm volatile("st.global.cg.f32 [%0], %1;" :: "l"(p), "f"(v) : "memory");
}
__device__ __forceinline__ void st16cg(__half* p, __half v) {
    unsigned short u = __half_as_ushort(v);
    asm volatile("st.global.cg.u16 [%0], %1;" :: "l"(p), "h"(u) : "memory");
}

#define LDSM4(R, addr) \
    asm volatile("ldmatrix.sync.aligned.m8n8.x4.shared.b16 {%0,%1,%2,%3}, [%4];" \
        : "=r"((R)[0]), "=r"((R)[1]), "=r"((R)[2]), "=r"((R)[3]) : "r"(addr))
#define MMA16816(C, A, B0R, B1R) \
    asm volatile("mma.sync.aligned.m16n8k16.row.col.f32.f16.f16.f32 " \
        "{%0,%1,%2,%3},{%4,%5,%6,%7},{%8,%9},{%0,%1,%2,%3};" \
        : "+f"((C)[0]), "+f"((C)[1]), "+f"((C)[2]), "+f"((C)[3]) \
        : "r"((A)[0]), "r"((A)[1]), "r"((A)[2]), "r"((A)[3]), "r"(B0R), "r"(B1R))
__device__ __forceinline__ void cpa16(uint32_t s, const void* g) {
    asm volatile("cp.async.cg.shared.global [%0], [%1], 16;" :: "r"(s), "l"(g));
}
#define CP_COMMIT() asm volatile("cp.async.commit_group;" ::: "memory")
#define CP_WAIT1()  asm volatile("cp.async.wait_group 1;" ::: "memory")
#define CP_WAIT0()  asm volatile("cp.async.wait_group 0;" ::: "memory")

// ---------------- init: zero state, tickets, barrier; seed out with b4 ----------------
__global__ void k_init(float* __restrict__ out, const float* __restrict__ b4) {
    int stride = gridDim.x * blockDim.x;
    int i0 = blockIdx.x * blockDim.x + threadIdx.x;
    __half z = __float2half(0.f);
    if (i0 < TT + 2) g_ticket[i0] = 0u;
    if (i0 == 0) g_barcnt = 0u;
    for (int i = i0; i < BB * HH; i += stride) {
        g_C0[i] = 0.f; g_C1[i] = 0.f;
        g_H0h[0][i] = z; g_H0l[0][i] = z;
        g_H1h[1][i] = z; g_H1l[1][i] = z;
    }
    float b40 = b4[0], b41 = b4[1];
    for (int i = i0; i < BB * TT * 2; i += stride)
        out[i] = (i & 1) ? b41 : b40;
}

// ---------------- weight image prep (single fp16 plane) ----------------
__global__ void k_prep(const float* __restrict__ Whh0, const float* __restrict__ Wih1,
                       const float* __restrict__ Whh1, const float* __restrict__ W3) {
    int stride = gridDim.x * blockDim.x;
    const int N0 = 8 * 128 * 256;
    const int N1 = 8 * 128 * 512;
    const int N3 = 128 * 256;
    const int TOT = N0 + N1 + N3;
    for (int idx = blockIdx.x * blockDim.x + threadIdx.x; idx < TOT; idx += stride) {
        float v; __half* D; int d;
        if (idx < N0) {
            int T = idx >> 15, r = idx & 32767;
            int n = r >> 8, k = r & 255;
            int row = (n & 3) * 256 + T * 32 + (n >> 2);   // gate-interleaved
            v = Whh0[row * 256 + k]; D = g_I0; d = idx;
        } else if (idx < N0 + N1) {
            int li = idx - N0;
            int T = li >> 16, r = li & 65535;
            int n = r >> 9, k = r & 511;
            int row = (n & 3) * 256 + T * 32 + (n >> 2);
            v = (k < 256) ? Wih1[row * 256 + k] : Whh1[row * 256 + (k - 256)];
            D = g_I1; d = li;
        } else {
            int li = idx - N0 - N1;
            v = W3[li]; D = g_I3; d = li;
        }
        D[d] = __float2half_rn(v);
    }
}

// ---------------- encoder ----------------
__global__ void k_enc1(const float* __restrict__ x,
                       const float* __restrict__ W1, const float* __restrict__ b1,
                       const float* __restrict__ g1, const float* __restrict__ be1) {
    int b = blockIdx.x, j = threadIdx.x;
    __shared__ float xs[5];
    __shared__ float red[128];
    if (j < 5) xs[j] = x[b * 5 + j];
    __syncthreads();
    float s = b1[j];
#pragma unroll
    for (int k = 0; k < 5; k++) s = fmaf(xs[k], W1[j * 5 + k], s);
    float gv = geluf(s);
    red[j] = gv; __syncthreads();
#pragma unroll
    for (int o = 64; o > 0; o >>= 1) { if (j < o) red[j] += red[j + o]; __syncthreads(); }
    float m = red[0] * (1.0f / 128.0f);
    __syncthreads();
    float d = gv - m; red[j] = d * d; __syncthreads();
#pragma unroll
    for (int o = 64; o > 0; o >>= 1) { if (j < o) red[j] += red[j + o]; __syncthreads(); }
    float v = red[0] * (1.0f / 128.0f);
    g_E1[b * 128 + j] = d * rsqrtf(v + LN_EPS) * g1[j] + be1[j];
}

__global__ void __launch_bounds__(256) k_enc2(const float* __restrict__ W2,
                                              const float* __restrict__ b2,
                                              const float* __restrict__ g2,
                                              const float* __restrict__ be2) {
    __shared__ float xs[8][129];
    __shared__ float W2c[64][129];
    __shared__ float go_[8][260];
    int b0 = blockIdx.x * 8;
    int tid = threadIdx.x;
#pragma unroll
    for (int i = 0; i < 4; i++) {
        int v = tid + i * 256;
        int r = v >> 7, c = v & 127;
        xs[r][c] = g_E1[(b0 + r) * 128 + c];
    }
    int col = tid & 63;
    int bg = tid >> 6;
    for (int cc = 0; cc < 4; cc++) {
        __syncthreads();
#pragma unroll
        for (int i = 0; i < 32; i++) {
            int v = tid + i * 256;
            int r = v >> 7, c = v & 127;
            W2c[r][c] = W2[(cc * 64 + r) * 128 + c];
        }
        __syncthreads();
        int gcol = cc * 64 + col;
        float s0 = b2[gcol], s1 = s0;
        const float* x0 = xs[bg * 2];
        const float* x1 = xs[bg * 2 + 1];
#pragma unroll 8
        for (int k = 0; k < 128; k++) {
            float w = W2c[col][k];
            s0 = fmaf(x0[k], w, s0);
            s1 = fmaf(x1[k], w, s1);
        }
        go_[bg * 2][gcol] = geluf(s0);
        go_[bg * 2 + 1][gcol] = geluf(s1);
    }
    __syncthreads();
    int w = tid >> 5, lane = tid & 31;
    float v8[8], s = 0.f;
#pragma unroll
    for (int i = 0; i < 8; i++) { v8[i] = go_[w][lane + 32 * i]; s += v8[i]; }
#pragma unroll
    for (int o = 16; o > 0; o >>= 1) s += __shfl_xor_sync(0xffffffffu, s, o);
    float m = s * (1.0f / 256.0f);
    float vv = 0.f;
#pragma unroll
    for (int i = 0; i < 8; i++) { float d = v8[i] - m; vv += d * d; }
#pragma unroll
    for (int o = 16; o > 0; o >>= 1) vv += __shfl_xor_sync(0xffffffffu, vv, o);
    float rs = rsqrtf(vv * (1.0f / 256.0f) + LN_EPS);
#pragma unroll
    for (int i = 0; i < 8; i++) {
        int c = lane + 32 * i;
        g_ENC[(b0 + w) * HH + c] = (v8[i] - m) * rs * g2[c] + be2[c];
    }
}

// ---------------- xp0 = enc @ Wih0^T + bih0 + bhh0 (fp32, once) ----------------
__global__ void __launch_bounds__(256, 2) k_xp0(const float* __restrict__ Wih0,
                                                const float* __restrict__ bih0,
                                                const float* __restrict__ bhh0) {
    __shared__ __align__(16) float As[32 * 36];
    __shared__ __align__(16) float Ws[32 * 260];
    const int SA = 36, SW = 260;
    float acc[4][8];
#pragma unroll
    for (int q = 0; q < 4; q++)
#pragma unroll
        for (int r = 0; r < 8; r++) acc[q][r] = 0.f;
    int b0 = (blockIdx.x >> 2) * 32, u0 = (blockIdx.x & 3) * 64;
    const int tid = threadIdx.x;
    const int u = tid % 64, rg = tid / 64;
    for (int kc = 0; kc < HH; kc += 32) {
        __syncthreads();
        {
            int row = tid >> 3, c4 = tid & 7;
            float4 f = *(const float4*)(g_ENC + (b0 + row) * HH + kc + c4 * 4);
            As[(c4 * 4 + 0) * SA + row] = f.x; As[(c4 * 4 + 1) * SA + row] = f.y;
            As[(c4 * 4 + 2) * SA + row] = f.z; As[(c4 * 4 + 3) * SA + row] = f.w;
        }
#pragma unroll
        for (int i = 0; i < 8; i++) {
            int v = tid + i * 256;
            int qu = v >> 3, c4 = v & 7;
            int q = qu & 3, uu = qu >> 2;
            float4 f = *(const float4*)(Wih0 + (q * HH + u0 + uu) * HH + kc + c4 * 4);
            Ws[(c4 * 4 + 0) * SW + uu * 4 + q] = f.x; Ws[(c4 * 4 + 1) * SW + uu * 4 + q] = f.y;
            Ws[(c4 * 4 + 2) * SW + uu * 4 + q] = f.z; Ws[(c4 * 4 + 3) * SW + uu * 4 + q] = f.w;
        }
        __syncthreads();
#pragma unroll
        for (int k = 0; k < 32; k++) {
            float4 a0 = *(const float4*)&As[k * SA + rg * 8];
            float4 a1 = *(const float4*)&As[k * SA + rg * 8 + 4];
            float4 wv = *(const float4*)&Ws[k * SW + u * 4];
            float av[8] = {a0.x, a0.y, a0.z, a0.w, a1.x, a1.y, a1.z, a1.w};
            float wq[4] = {wv.x, wv.y, wv.z, wv.w};
#pragma unroll
            for (int q = 0; q < 4; q++)
#pragma unroll
                for (int r = 0; r < 8; r++)
                    acc[q][r] = fmaf(wq[q], av[r], acc[q][r]);
        }
    }
    int ug = u0 + u;
#pragma unroll
    for (int q = 0; q < 4; q++) {
        float bs = bih0[q * HH + ug] + bhh0[q * HH + ug];
#pragma unroll
        for (int r = 0; r < 8; r++) {
            int b = b0 + rg * 8 + r;
            g_XP0[b * (4 * HH) + q * HH + ug] = acc[q][r] + bs;
        }
    }
}

// ---------------- persistent kernel: all T steps, grid barrier + work stealing ----------
// Jobs per step (544): [0,256) role1 (layer1 t-1), [256,512) role0 (layer0 t),
// [512,544) role2 (decoder t-2). Each job = 128x64 output tile, fp16 2-pass HMMA.
// CTA = 128 threads, 4 warps (2m x 2n), warp tile 64x32, double-buffered cp.async.
__global__ void __launch_bounds__(128, 4) k_persist(
    const float* __restrict__ bih1, const float* __restrict__ bhh1,
    const float* __restrict__ b3, const float* __restrict__ W4,
    float* __restrict__ out) {
    extern __shared__ __align__(16) char SMEM[];
    float* sD = (float*)SMEM;                    // 128 x 68 floats epilogue dump (overlay)
    const uint32_t smem0 = smem_u32(SMEM);
    const int tid = threadIdx.x;
    const int lane = tid & 31, wid = tid >> 5;
    const int m0 = (wid & 1) * 64, n0 = (wid >> 1) * 32;
    __shared__ int sj;

    const uint32_t aHo = (uint32_t)(((m0 + (lane & 7) + ((lane >> 3) & 1) * 8) * 40 +
                                     ((lane >> 4) & 1) * 8) * 2);
    const uint32_t bHo = 20480u + (uint32_t)(((n0 + ((lane >> 4) & 1) * 8 + (lane & 7)) * 40 +
                                              ((lane >> 3) & 1) * 8) * 2);
    const int brow = tid >> 1, bh2 = tid & 1;

    for (int t = 0; t <= TT + 1; t++) {
        const int p = t & 1;
        // ---- steal jobs for this step ----
        for (;;) {
            __syncthreads();
            if (tid == 0) sj = (int)atomicAdd(&g_ticket[t], 1u);
            __syncthreads();
            int j = sj;
            if (j >= NJOBS) break;

            int role, mt, Tc;
            if (j < 256)      { if (t < 1 || t > TT) continue; role = 1; mt = j >> 4; Tc = j & 15; }
            else if (j < 512) { if (t >= TT) continue; role = 0; int l = j - 256; mt = l >> 4; Tc = l & 15; }
            else              { if (t < 2) continue; role = 2; int l = j - 512; mt = l >> 1; Tc = l & 1; }
            const int b0 = mt * 128;

            const __half *A0h, *A0l, *A1h = 0, *A1l = 0, *Bi;
            int Kb, nch;
            if (role == 1) {
                A0h = g_H0h[p]; A0l = g_H0l[p];
                A1h = g_H1h[p]; A1l = g_H1l[p];
                Bi = g_I1 + ((size_t)(Tc >> 1) * 128 + (size_t)(Tc & 1) * 64) * 512;
                Kb = 512; nch = 16;
            } else if (role == 0) {
                A0h = g_H0h[p]; A0l = g_H0l[p];
                Bi = g_I0 + ((size_t)(Tc >> 1) * 128 + (size_t)(Tc & 1) * 64) * 256;
                Kb = 256; nch = 8;
            } else {
                A0h = g_H1h[p]; A0l = g_H1l[p];
                Bi = g_I3 + (size_t)Tc * 64 * 256;
                Kb = 256; nch = 8;
            }

            float C[4][4][4];
#pragma unroll
            for (int f = 0; f < 4; f++)
#pragma unroll
                for (int g = 0; g < 4; g++)
#pragma unroll
                    for (int i = 0; i < 4; i++) C[f][g][i] = 0.f;

            auto issue_load = [&](int ch) {
                const __half *gah, *gal; int kc;
                if (role == 1 && ch >= 8) { gah = A1h; gal = A1l; kc = (ch - 8) * 32; }
                else                      { gah = A0h; gal = A0l; kc = (ch & 7) * 32; }
                int bk = ch * 32;
                uint32_t base = smem0 + (uint32_t)(ch & 1) * BUFB;
                uint32_t sa = base + (uint32_t)tid * 80u;
                const __half* gh = gah + (size_t)(b0 + tid) * HH + kc;
                const __half* gl = gal + (size_t)(b0 + tid) * HH + kc;
#pragma unroll
                for (int q = 0; q < 4; q++) {
                    cpa16(sa + (uint32_t)q * 16u, gh + q * 8);
                    cpa16(sa + 10240u + (uint32_t)q * 16u, gl + q * 8);
                }
                const __half* gb = Bi + (size_t)brow * Kb + bk + bh2 * 16;
                uint32_t sb = base + 20480u + (uint32_t)brow * 80u + (uint32_t)bh2 * 32u;
                cpa16(sb, gb);
                cpa16(sb + 16u, gb + 8);
                CP_COMMIT();
            };

            issue_load(0);
            for (int ch = 0; ch < nch; ch++) {
                if (ch + 1 < nch) { issue_load(ch + 1); CP_WAIT1(); }
                else              { CP_WAIT0(); }
                __syncthreads();
                uint32_t base = smem0 + (uint32_t)(ch & 1) * BUFB;
                uint32_t aH = base + aHo, aL = aH + 10240u;
                uint32_t bH = base + bHo;
#pragma unroll
                for (int ks = 0; ks < 2; ks++) {
                    uint32_t Af[4][4], Alr[4][4], Bq[8];
#pragma unroll
                    for (int f = 0; f < 4; f++) LDSM4(Af[f], aH + (uint32_t)(f * 1280 + ks * 32));
#pragma unroll
                    for (int f = 0; f < 4; f++) LDSM4(Alr[f], aL + (uint32_t)(f * 1280 + ks * 32));
                    LDSM4(&Bq[0], bH + (uint32_t)(ks * 32));
                    LDSM4(&Bq[4], bH + (uint32_t)(1280 + ks * 32));
#pragma unroll
                    for (int f = 0; f < 4; f++)
#pragma unroll
                        for (int g = 0; g < 4; g++)
                            MMA16816(C[f][g], Af[f], Bq[2 * g], Bq[2 * g + 1]);
#pragma unroll
                    for (int f = 0; f < 4; f++)
#pragma unroll
                        for (int g = 0; g < 4; g++)
                            MMA16816(C[f][g], Alr[f], Bq[2 * g], Bq[2 * g + 1]);
                }
                __syncthreads();
            }

            // ---- epilogue: C -> smem ----
#pragma unroll
            for (int f = 0; f < 4; f++) {
                int r = m0 + f * 16 + (lane >> 2);
#pragma unroll
                for (int g = 0; g < 4; g++) {
                    int c = n0 + g * 8 + (lane & 3) * 2;
                    sD[r * 68 + c]           = C[f][g][0];
                    sD[r * 68 + c + 1]       = C[f][g][1];
                    sD[(r + 8) * 68 + c]     = C[f][g][2];
                    sD[(r + 8) * 68 + c + 1] = C[f][g][3];
                }
            }
            __syncthreads();

            if (role == 2) {
                int b = b0 + tid;
                int ts = t - 2;
                float p0 = 0.f, p1 = 0.f;
#pragma unroll
                for (int c4 = 0; c4 < 16; c4++) {
                    float4 v4 = *(const float4*)&sD[tid * 68 + c4 * 4];
                    int col = Tc * 64 + c4 * 4;
                    float d0 = geluf(v4.x + b3[col]);
                    float d1 = geluf(v4.y + b3[col + 1]);
                    float d2 = geluf(v4.z + b3[col + 2]);
                    float d3 = geluf(v4.w + b3[col + 3]);
                    p0 = fmaf(d0, W4[col], p0);       p1 = fmaf(d0, W4[128 + col], p1);
                    p0 = fmaf(d1, W4[col + 1], p0);   p1 = fmaf(d1, W4[129 + col], p1);
                    p0 = fmaf(d2, W4[col + 2], p0);   p1 = fmaf(d2, W4[130 + col], p1);
                    p0 = fmaf(d3, W4[col + 3], p0);   p1 = fmaf(d3, W4[131 + col], p1);
                }
                atomicAdd(&out[b * (TT * 2) + ts * 2 + 0], p0);
                atomicAdd(&out[b * (TT * 2) + ts * 2 + 1], p1);
            } else {
                int ul = tid & 15;
                int u = Tc * 16 + ul;
                float* Cst = (role == 0) ? g_C0 : g_C1;
                __half* Hh = (role == 0) ? g_H0h[1 - p] : g_H1h[1 - p];
                __half* Hl = (role == 0) ? g_H0l[1 - p] : g_H1l[1 - p];
                float bsi = 0.f, bsf = 0.f, bsg = 0.f, bso = 0.f;
                if (role == 1) {
                    bsi = bih1[u] + bhh1[u];
                    bsf = bih1[256 + u] + bhh1[256 + u];
                    bsg = bih1[512 + u] + bhh1[512 + u];
                    bso = bih1[768 + u] + bhh1[768 + u];
                }
#pragma unroll
                for (int i = 0; i < 16; i++) {
                    int row = (tid >> 4) * 16 + i;
                    int b = b0 + row;
                    float4 gv = *(const float4*)&sD[row * 68 + ul * 4];
                    float pi, pf, pg, po;
                    if (role == 0) {
                        const float* xp = g_XP0 + (size_t)b * 1024;
                        pi = gv.x + xp[u]; pf = gv.y + xp[256 + u];
                        pg = gv.z + xp[512 + u]; po = gv.w + xp[768 + u];
                    } else {
                        pi = gv.x + bsi; pf = gv.y + bsf; pg = gv.z + bsg; po = gv.w + bso;
                    }
                    float gi = sigf(pi), gf = sigf(pf), gg = tanhf(pg), go = sigf(po);
                    int ci = b * HH + u;
                    float c = gf * ld32cg(Cst + ci) + gi * gg;
                    st32cg(Cst + ci, c);
                    float h = go * tanhf(c);
                    __half h16 = __float2half_rn(h);
                    st16cg(Hh + ci, h16);
                    st16cg(Hl + ci, __float2half_rn(h - __half2float(h16)));
                }
            }
            __syncthreads();
        }

        // ---- grid barrier (monotonic counter) ----
        __threadfence();
        __syncthreads();
        if (tid == 0) {
            atomicAdd(&g_barcnt, 1u);
            unsigned tgt = (unsigned)gridDim.x * (unsigned)(t + 1);
            for (;;) {
                unsigned v;
                asm volatile("ld.global.cg.u32 %0, [%1];" : "=r"(v) : "l"(&g_barcnt));
                if (v >= tgt) break;
                __nanosleep(128);
            }
        }
        __syncthreads();
    }
}

extern "C" void kernel_launch(void* const* d_in, const int* in_sizes, int n_in,
                              void* d_out, int out_size) {
    const float* x    = (const float*)d_in[0];
    const float* W1   = (const float*)d_in[1];
    const float* b1   = (const float*)d_in[2];
    const float* g1   = (const float*)d_in[3];
    const float* be1  = (const float*)d_in[4];
    const float* W2   = (const float*)d_in[5];
    const float* b2   = (const float*)d_in[6];
    const float* g2   = (const float*)d_in[7];
    const float* be2  = (const float*)d_in[8];
    const float* Wih0 = (const float*)d_in[9];
    const float* Whh0 = (const float*)d_in[10];
    const float* bih0 = (const float*)d_in[11];
    const float* bhh0 = (const float*)d_in[12];
    const float* Wih1 = (const float*)d_in[13];
    const float* Whh1 = (const float*)d_in[14];
    const float* bih1 = (const float*)d_in[15];
    const float* bhh1 = (const float*)d_in[16];
    const float* W3   = (const float*)d_in[17];
    const float* b3   = (const float*)d_in[18];
    const float* W4   = (const float*)d_in[19];
    const float* b4   = (const float*)d_in[20];
    float* out = (float*)d_out;

    static int grid_p = 0;
    if (!grid_p) {
        cudaFuncSetAttribute(k_persist, cudaFuncAttributeMaxDynamicSharedMemorySize, 2 * BUFB);
        int dev = 0, nsm = 148, nb = 0;
        cudaGetDevice(&dev);
        cudaDeviceGetAttribute(&nsm, cudaDevAttrMultiProcessorCount, dev);
        cudaOccupancyMaxActiveBlocksPerMultiprocessor(&nb, k_persist, 128, 2 * BUFB);
        if (nb < 1) nb = 1;
        if (nb > 4) nb = 4;
        grid_p = nsm * nb;
    }

    k_init<<<512, 256>>>(out, b4);
    k_prep<<<832, 256>>>(Whh0, Wih1, Whh1, W3);
    k_enc1<<<BB, 128>>>(x, W1, b1, g1, be1);
    k_enc2<<<256, 256>>>(W2, b2, g2, be2);
    k_xp0<<<256, 256>>>(Wih0, bih0, bhh0);
    k_persist<<<grid_p, 128, 2 * BUFB>>>(bih1, bhh1, b3, W4, out);
}

// round 16
// speedup vs baseline: 2.4958x; 2.4958x over previous
#include <cuda_runtime.h>
#include <cuda_fp16.h>
#include <math.h>
#include <stdint.h>

#define BB 2048
#define HH 256
#define TT 256
#define LN_EPS 1e-5f

// ---------------- persistent device scratch (no allocations) ----------------
__device__ float g_C0[BB * HH], g_C1[BB * HH];
__device__ __align__(16) __half g_H0[2][BB * HH];
__device__ __align__(16) __half g_H1[2][BB * HH];
__device__ float g_XP0[BB * 4 * HH];
__device__ float g_E1[BB * 128], g_ENC[BB * HH];
// fp16 weight images: gate-interleaved row-major [tile][n][K], single plane
__device__ __align__(16) __half g_I0[8 * 128 * 256];   // Whh0
__device__ __align__(16) __half g_I1[8 * 128 * 512];   // [Wih1 | Whh1]
__device__ __align__(16) __half g_I3[128 * 256];       // W3

__device__ __forceinline__ float geluf(float v) {
    return 0.5f * v * (1.0f + erff(v * 0.7071067811865476f));
}
__device__ __forceinline__ float sigf(float v) { return 1.0f / (1.0f + expf(-v)); }

__device__ __forceinline__ uint32_t smem_u32(const void* p) {
    uint32_t a;
    asm("{ .reg .u64 t; cvta.to.shared.u64 t, %1; cvt.u32.u64 %0, t; }" : "=r"(a) : "l"(p));
    return a;
}

#define LDSM4(R, addr) \
    asm volatile("ldmatrix.sync.aligned.m8n8.x4.shared.b16 {%0,%1,%2,%3}, [%4];" \
        : "=r"((R)[0]), "=r"((R)[1]), "=r"((R)[2]), "=r"((R)[3]) : "r"(addr))
#define MMA16816(C, A, B0R, B1R) \
    asm volatile("mma.sync.aligned.m16n8k16.row.col.f32.f16.f16.f32 " \
        "{%0,%1,%2,%3},{%4,%5,%6,%7},{%8,%9},{%0,%1,%2,%3};" \
        : "+f"((C)[0]), "+f"((C)[1]), "+f"((C)[2]), "+f"((C)[3]) \
        : "r"((A)[0]), "r"((A)[1]), "r"((A)[2]), "r"((A)[3]), "r"(B0R), "r"(B1R))
__device__ __forceinline__ void cpa16(uint32_t s, const void* g) {
    asm volatile("cp.async.cg.shared.global [%0], [%1], 16;" :: "r"(s), "l"(g));
}
#define CP_COMMIT() asm volatile("cp.async.commit_group;" ::: "memory")
#define CP_WAIT1()  asm volatile("cp.async.wait_group 1;" ::: "memory")
#define CP_WAIT0()  asm volatile("cp.async.wait_group 0;" ::: "memory")

// ---------------- init ----------------
__global__ void k_init() {
    int stride = gridDim.x * blockDim.x;
    __half z = __float2half(0.f);
    for (int i = blockIdx.x * blockDim.x + threadIdx.x; i < BB * HH; i += stride) {
        g_C0[i] = 0.f; g_C1[i] = 0.f;
        g_H0[0][i] = z; g_H1[1][i] = z;
    }
}

// ---------------- weight image prep (single fp16 plane) ----------------
__global__ void k_prep(const float* __restrict__ Whh0, const float* __restrict__ Wih1,
                       const float* __restrict__ Whh1, const float* __restrict__ W3) {
    int stride = gridDim.x * blockDim.x;
    const int N0 = 8 * 128 * 256;
    const int N1 = 8 * 128 * 512;
    const int N3 = 128 * 256;
    const int TOT = N0 + N1 + N3;
    for (int idx = blockIdx.x * blockDim.x + threadIdx.x; idx < TOT; idx += stride) {
        float v; __half* D; int d;
        if (idx < N0) {
            int T = idx >> 15, r = idx & 32767;
            int n = r >> 8, k = r & 255;
            int row = (n & 3) * 256 + T * 32 + (n >> 2);   // gate-interleaved
            v = Whh0[row * 256 + k]; D = g_I0; d = idx;
        } else if (idx < N0 + N1) {
            int li = idx - N0;
            int T = li >> 16, r = li & 65535;
            int n = r >> 9, k = r & 511;
            int row = (n & 3) * 256 + T * 32 + (n >> 2);
            v = (k < 256) ? Wih1[row * 256 + k] : Whh1[row * 256 + (k - 256)];
            D = g_I1; d = li;
        } else {
            int li = idx - N0 - N1;
            v = W3[li]; D = g_I3; d = li;
        }
        D[d] = __float2half_rn(v);
    }
}

// ---------------- encoder ----------------
__global__ void k_enc1(const float* __restrict__ x,
                       const float* __restrict__ W1, const float* __restrict__ b1,
                       const float* __restrict__ g1, const float* __restrict__ be1) {
    int b = blockIdx.x, j = threadIdx.x;
    __shared__ float xs[5];
    __shared__ float red[128];
    if (j < 5) xs[j] = x[b * 5 + j];
    __syncthreads();
    float s = b1[j];
#pragma unroll
    for (int k = 0; k < 5; k++) s = fmaf(xs[k], W1[j * 5 + k], s);
    float gv = geluf(s);
    red[j] = gv; __syncthreads();
#pragma unroll
    for (int o = 64; o > 0; o >>= 1) { if (j < o) red[j] += red[j + o]; __syncthreads(); }
    float m = red[0] * (1.0f / 128.0f);
    __syncthreads();
    float d = gv - m; red[j] = d * d; __syncthreads();
#pragma unroll
    for (int o = 64; o > 0; o >>= 1) { if (j < o) red[j] += red[j + o]; __syncthreads(); }
    float v = red[0] * (1.0f / 128.0f);
    g_E1[b * 128 + j] = d * rsqrtf(v + LN_EPS) * g1[j] + be1[j];
}

__global__ void __launch_bounds__(256) k_enc2(const float* __restrict__ W2,
                                              const float* __restrict__ b2,
                                              const float* __restrict__ g2,
                                              const float* __restrict__ be2) {
    __shared__ float xs[8][129];
    __shared__ float W2c[64][129];
    __shared__ float go_[8][260];
    int b0 = blockIdx.x * 8;
    int tid = threadIdx.x;
#pragma unroll
    for (int i = 0; i < 4; i++) {
        int v = tid + i * 256;
        int r = v >> 7, c = v & 127;
        xs[r][c] = g_E1[(b0 + r) * 128 + c];
    }
    int col = tid & 63;
    int bg = tid >> 6;
    for (int cc = 0; cc < 4; cc++) {
        __syncthreads();
#pragma unroll
        for (int i = 0; i < 32; i++) {
            int v = tid + i * 256;
            int r = v >> 7, c = v & 127;
            W2c[r][c] = W2[(cc * 64 + r) * 128 + c];
        }
        __syncthreads();
        int gcol = cc * 64 + col;
        float s0 = b2[gcol], s1 = s0;
        const float* x0 = xs[bg * 2];
        const float* x1 = xs[bg * 2 + 1];
#pragma unroll 8
        for (int k = 0; k < 128; k++) {
            float w = W2c[col][k];
            s0 = fmaf(x0[k], w, s0);
            s1 = fmaf(x1[k], w, s1);
        }
        go_[bg * 2][gcol] = geluf(s0);
        go_[bg * 2 + 1][gcol] = geluf(s1);
    }
    __syncthreads();
    int w = tid >> 5, lane = tid & 31;
    float v8[8], s = 0.f;
#pragma unroll
    for (int i = 0; i < 8; i++) { v8[i] = go_[w][lane + 32 * i]; s += v8[i]; }
#pragma unroll
    for (int o = 16; o > 0; o >>= 1) s += __shfl_xor_sync(0xffffffffu, s, o);
    float m = s * (1.0f / 256.0f);
    float vv = 0.f;
#pragma unroll
    for (int i = 0; i < 8; i++) { float d = v8[i] - m; vv += d * d; }
#pragma unroll
    for (int o = 16; o > 0; o >>= 1) vv += __shfl_xor_sync(0xffffffffu, vv, o);
    float rs = rsqrtf(vv * (1.0f / 256.0f) + LN_EPS);
#pragma unroll
    for (int i = 0; i < 8; i++) {
        int c = lane + 32 * i;
        g_ENC[(b0 + w) * HH + c] = (v8[i] - m) * rs * g2[c] + be2[c];
    }
}

// ---------------- xp0 = enc @ Wih0^T + bih0 + bhh0 (fp32, once) ----------------
__global__ void __launch_bounds__(256, 2) k_xp0(const float* __restrict__ Wih0,
                                                const float* __restrict__ bih0,
                                                const float* __restrict__ bhh0) {
    __shared__ __align__(16) float As[32 * 36];
    __shared__ __align__(16) float Ws[32 * 260];
    const int SA = 36, SW = 260;
    float acc[4][8];
#pragma unroll
    for (int q = 0; q < 4; q++)
#pragma unroll
        for (int r = 0; r < 8; r++) acc[q][r] = 0.f;
    int b0 = (blockIdx.x >> 2) * 32, u0 = (blockIdx.x & 3) * 64;
    const int tid = threadIdx.x;
    const int u = tid % 64, rg = tid / 64;
    for (int kc = 0; kc < HH; kc += 32) {
        __syncthreads();
        {
            int row = tid >> 3, c4 = tid & 7;
            float4 f = *(const float4*)(g_ENC + (b0 + row) * HH + kc + c4 * 4);
            As[(c4 * 4 + 0) * SA + row] = f.x; As[(c4 * 4 + 1) * SA + row] = f.y;
            As[(c4 * 4 + 2) * SA + row] = f.z; As[(c4 * 4 + 3) * SA + row] = f.w;
        }
#pragma unroll
        for (int i = 0; i < 8; i++) {
            int v = tid + i * 256;
            int qu = v >> 3, c4 = v & 7;
            int q = qu & 3, uu = qu >> 2;
            float4 f = *(const float4*)(Wih0 + (q * HH + u0 + uu) * HH + kc + c4 * 4);
            Ws[(c4 * 4 + 0) * SW + uu * 4 + q] = f.x; Ws[(c4 * 4 + 1) * SW + uu * 4 + q] = f.y;
            Ws[(c4 * 4 + 2) * SW + uu * 4 + q] = f.z; Ws[(c4 * 4 + 3) * SW + uu * 4 + q] = f.w;
        }
        __syncthreads();
#pragma unroll
        for (int k = 0; k < 32; k++) {
            float4 a0 = *(const float4*)&As[k * SA + rg * 8];
            float4 a1 = *(const float4*)&As[k * SA + rg * 8 + 4];
            float4 wv = *(const float4*)&Ws[k * SW + u * 4];
            float av[8] = {a0.x, a0.y, a0.z, a0.w, a1.x, a1.y, a1.z, a1.w};
            float wq[4] = {wv.x, wv.y, wv.z, wv.w};
#pragma unroll
            for (int q = 0; q < 4; q++)
#pragma unroll
                for (int r = 0; r < 8; r++)
                    acc[q][r] = fmaf(wq[q], av[r], acc[q][r]);
        }
    }
    int ug = u0 + u;
#pragma unroll
    for (int q = 0; q < 4; q++) {
        float bs = bih0[q * HH + ug] + bhh0[q * HH + ug];
#pragma unroll
        for (int r = 0; r < 8; r++) {
            int b = b0 + rg * 8 + r;
            g_XP0[b * (4 * HH) + q * HH + ug] = acc[q][r] + bs;
        }
    }
}

// ---------------- per-step kernel: layer0(t) | layer1(t-1) | decoder(t-2) ----------------
// CTA 128x128 tile, 8 warps (2M x 4N), warp tile 64x32. fp16 SINGLE-pass (A*B).
// Double-buffered cp.async; buffer = 2 tiles (A, B) 128x32 fp16, padded stride 40.
#define BUFB 20480
__global__ void __launch_bounds__(256, 2) k_step(int t,
    const float* __restrict__ bih1, const float* __restrict__ bhh1,
    const float* __restrict__ b3, const float* __restrict__ W4,
    const float* __restrict__ b4, float* __restrict__ out) {
    int bid = blockIdx.x;
    int role;
    if (bid < 128)      { if (t >= TT) return;          role = 0; }
    else if (bid < 256) { if (t < 1 || t > TT) return;  role = 1; }
    else                { if (t < 2) return;            role = 2; }
    const int p = t & 1;
    const int tid = threadIdx.x;
    const int lane = tid & 31, wid = tid >> 5;
    const int wm = wid & 1, wn = wid >> 1;
    const int m0 = wm * 64, n0 = wn * 32;

    extern __shared__ __align__(16) char SMEM[];
    float* sD = (float*)SMEM;          // epilogue dump: 128 x 68 floats (overlay)
    const uint32_t smem0 = smem_u32(SMEM);

    // role-dependent sources
    const __half *A0, *A1 = 0, *Bi;
    int bstride, nch, b0, T = 0;
    if (role == 0) {
        int mt = bid >> 3; T = bid & 7;
        b0 = mt * 128;
        A0 = g_H0[p];
        Bi = g_I0 + (size_t)T * 32768;
        bstride = 256; nch = 8;
    } else if (role == 1) {
        int lb = bid - 128;
        int mt = lb >> 3; T = lb & 7;
        b0 = mt * 128;
        A0 = g_H0[p];
        A1 = g_H1[p];
        Bi = g_I1 + (size_t)T * 65536;
        bstride = 512; nch = 16;
    } else {
        b0 = (bid - 256) * 128;
        A0 = g_H1[p];
        Bi = g_I3;
        bstride = 256; nch = 8;
    }

    float C[4][4][4];
#pragma unroll
    for (int f = 0; f < 4; f++)
#pragma unroll
        for (int g = 0; g < 4; g++)
#pragma unroll
            for (int i = 0; i < 4; i++) C[f][g][i] = 0.f;

    // cp.async issue for chunk ch into buffer ch&1 (4 x 16B per thread)
    const int ldrow = tid >> 2, ldq = tid & 3;
    auto issue_load = [&](int ch) {
        const __half* ga;
        int kc, bk;
        if (role == 1 && ch >= 8) { ga = A1; kc = (ch - 8) * 32; bk = 256 + (ch - 8) * 32; }
        else                      { ga = A0; kc = ch * 32; bk = ch * 32; }
        uint32_t base = smem0 + (uint32_t)(ch & 1) * BUFB;
#pragma unroll
        for (int i = 0; i < 2; i++) {
            int row = ldrow + i * 64;
            uint32_t soff = (uint32_t)(row * 40 + ldq * 8) * 2u;
            cpa16(base + soff,          ga + (size_t)(b0 + row) * HH + kc + ldq * 8);
            cpa16(base + 10240u + soff, Bi + (size_t)row * bstride + bk + ldq * 8);
        }
        CP_COMMIT();
    };

    // ldmatrix thread addresses (byte offsets within a buffer)
    uint32_t aHo = (uint32_t)(((m0 + (lane & 7) + ((lane >> 3) & 1) * 8) * 40 +
                               ((lane >> 4) & 1) * 8) * 2);
    uint32_t bHo = 10240u + (uint32_t)(((n0 + ((lane >> 4) & 1) * 8 + (lane & 7)) * 40 +
                                        ((lane >> 3) & 1) * 8) * 2);

    issue_load(0);
    for (int ch = 0; ch < nch; ch++) {
        if (ch + 1 < nch) { issue_load(ch + 1); CP_WAIT1(); }
        else              { CP_WAIT0(); }
        __syncthreads();
        uint32_t base = smem0 + (uint32_t)(ch & 1) * BUFB;
        uint32_t aH = base + aHo;
        uint32_t bH = base + bHo;
#pragma unroll
        for (int ks = 0; ks < 2; ks++) {
            uint32_t Af[4][4], Bq[8];
#pragma unroll
            for (int f = 0; f < 4; f++) LDSM4(Af[f], aH + (uint32_t)(f * 1280 + ks * 32));
            LDSM4(&Bq[0], bH + (uint32_t)(ks * 32));
            LDSM4(&Bq[4], bH + (uint32_t)(1280 + ks * 32));
#pragma unroll
            for (int f = 0; f < 4; f++)
#pragma unroll
                for (int g = 0; g < 4; g++) MMA16816(C[f][g], Af[f], Bq[2 * g], Bq[2 * g + 1]);
        }
        __syncthreads();
    }

    // ---- epilogue: stage C through smem in two 64-col halves ----
    const int lane2 = lane & 3;
    float p0 = 0.f, p1 = 0.f;    // decoder accumulators (threads 0..127)
#pragma unroll
    for (int hh = 0; hh < 2; hh++) {
        __syncthreads();
        if ((wn >> 1) == hh) {
#pragma unroll
            for (int f = 0; f < 4; f++) {
                int r = m0 + f * 16 + (lane >> 2);
#pragma unroll
                for (int g = 0; g < 4; g++) {
                    int cl = (n0 & 63) + 8 * g + 2 * lane2;
                    sD[r * 68 + cl]           = C[f][g][0];
                    sD[r * 68 + cl + 1]       = C[f][g][1];
                    sD[(r + 8) * 68 + cl]     = C[f][g][2];
                    sD[(r + 8) * 68 + cl + 1] = C[f][g][3];
                }
            }
        }
        __syncthreads();
        if (role == 2) {
            if (tid < 128) {
#pragma unroll
                for (int c4 = 0; c4 < 16; c4++) {
                    float4 v4 = *(const float4*)&sD[tid * 68 + c4 * 4];
                    int col = hh * 64 + c4 * 4;
                    float d0 = geluf(v4.x + b3[col]);
                    float d1 = geluf(v4.y + b3[col + 1]);
                    float d2 = geluf(v4.z + b3[col + 2]);
                    float d3 = geluf(v4.w + b3[col + 3]);
                    p0 = fmaf(d0, W4[col], p0);       p1 = fmaf(d0, W4[128 + col], p1);
                    p0 = fmaf(d1, W4[col + 1], p0);   p1 = fmaf(d1, W4[129 + col], p1);
                    p0 = fmaf(d2, W4[col + 2], p0);   p1 = fmaf(d2, W4[130 + col], p1);
                    p0 = fmaf(d3, W4[col + 3], p0);   p1 = fmaf(d3, W4[131 + col], p1);
                }
            }
        } else {
            int ut = tid & 15, rg = tid >> 4;
            int u = T * 32 + hh * 16 + ut;
            float* Cst = (role == 0) ? g_C0 : g_C1;
            __half* Hh = (role == 0) ? g_H0[1 - p] : g_H1[1 - p];
            float bsi = 0.f, bsf = 0.f, bsg = 0.f, bso = 0.f;
            if (role == 1) {
                bsi = bih1[u] + bhh1[u];
                bsf = bih1[256 + u] + bhh1[256 + u];
                bsg = bih1[512 + u] + bhh1[512 + u];
                bso = bih1[768 + u] + bhh1[768 + u];
            }
#pragma unroll
            for (int r = 0; r < 8; r++) {
                int row = rg * 8 + r;
                int b = b0 + row;
                float4 gv = *(const float4*)&sD[row * 68 + ut * 4];
                float pi, pf, pg, po;
                if (role == 0) {
                    const float* xp = g_XP0 + (size_t)b * 1024;
                    pi = gv.x + xp[u]; pf = gv.y + xp[256 + u];
                    pg = gv.z + xp[512 + u]; po = gv.w + xp[768 + u];
                } else {
                    pi = gv.x + bsi; pf = gv.y + bsf; pg = gv.z + bsg; po = gv.w + bso;
                }
                float gi = sigf(pi), gf = sigf(pf), gg = tanhf(pg), go = sigf(po);
                int ci = b * HH + u;
                float c = gf * Cst[ci] + gi * gg;
                Cst[ci] = c;
                float h = go * tanhf(c);
                Hh[ci] = __float2half_rn(h);
            }
        }
    }
    if (role == 2 && tid < 128) {
        int ts = t - 2;
        int b = b0 + tid;
        out[b * (TT * 2) + ts * 2 + 0] = p0 + b4[0];
        out[b * (TT * 2) + ts * 2 + 1] = p1 + b4[1];
    }
}

extern "C" void kernel_launch(void* const* d_in, const int* in_sizes, int n_in,
                              void* d_out, int out_size) {
    const float* x    = (const float*)d_in[0];
    const float* W1   = (const float*)d_in[1];
    const float* b1   = (const float*)d_in[2];
    const float* g1   = (const float*)d_in[3];
    const float* be1  = (const float*)d_in[4];
    const float* W2   = (const float*)d_in[5];
    const float* b2   = (const float*)d_in[6];
    const float* g2   = (const float*)d_in[7];
    const float* be2  = (const float*)d_in[8];
    const float* Wih0 = (const float*)d_in[9];
    const float* Whh0 = (const float*)d_in[10];
    const float* bih0 = (const float*)d_in[11];
    const float* bhh0 = (const float*)d_in[12];
    const float* Wih1 = (const float*)d_in[13];
    const float* Whh1 = (const float*)d_in[14];
    const float* bih1 = (const float*)d_in[15];
    const float* bhh1 = (const float*)d_in[16];
    const float* W3   = (const float*)d_in[17];
    const float* b3   = (const float*)d_in[18];
    const float* W4   = (const float*)d_in[19];
    const float* b4   = (const float*)d_in[20];
    float* out = (float*)d_out;

    static int smem_set = 0;
    if (!smem_set) {
        cudaFuncSetAttribute(k_step, cudaFuncAttributeMaxDynamicSharedMemorySize, 2 * BUFB);
        smem_set = 1;
    }

    k_init<<<512, 256>>>();
    k_prep<<<832, 256>>>(Whh0, Wih1, Whh1, W3);
    k_enc1<<<BB, 128>>>(x, W1, b1, g1, be1);
    k_enc2<<<256, 256>>>(W2, b2, g2, be2);
    k_xp0<<<256, 256>>>(Wih0, bih0, bhh0);

    for (int t = 0; t <= TT + 1; t++) {
        k_step<<<272, 256, 2 * BUFB>>>(t, bih1, bhh1, b3, W4, b4, out);
    }
}